// round 16
// baseline (speedup 1.0000x reference)
#include <cuda_runtime.h>
#include <cuda_fp16.h>
#include <cstdint>

#define NQ 8192
#define D 32
#define DV 64
#define KNB 4
#define IN_DIM 256

#define BM 64
#define BN 128
#define NITER (NQ / BN)   // 64
#define QSB 80            // Q/K row: 64B data + 16B pad
#define VSB 272           // V row: 256B data + 16B pad

// ---------------- device scratch ----------------
__device__ __half g_Qs[2 * NQ * 32];          // [side][row][0..31] fp16
__device__ __half g_Vth[2 * DV * NQ];         // [side][n][j] fp16

// ---------------- PTX helpers ----------------
__device__ __forceinline__ uint32_t smem_u32(const void* p) {
    uint32_t a;
    asm("{ .reg .u64 t; cvta.to.shared.u64 t, %1; cvt.u32.u64 %0, t; }" : "=r"(a) : "l"(p));
    return a;
}
__device__ __forceinline__ void ldsm4(uint32_t r[4], uint32_t addr) {
    asm volatile("ldmatrix.sync.aligned.m8n8.x4.shared.b16 {%0,%1,%2,%3}, [%4];"
                 : "=r"(r[0]), "=r"(r[1]), "=r"(r[2]), "=r"(r[3]) : "r"(addr));
}
__device__ __forceinline__ void mma_fp16(float d[4], const uint32_t a[4], const uint32_t b[2]) {
    asm volatile(
        "mma.sync.aligned.m16n8k16.row.col.f32.f16.f16.f32 "
        "{%0,%1,%2,%3}, {%4,%5,%6,%7}, {%8,%9}, {%0,%1,%2,%3};"
        : "+f"(d[0]), "+f"(d[1]), "+f"(d[2]), "+f"(d[3])
        : "r"(a[0]), "r"(a[1]), "r"(a[2]), "r"(a[3]), "r"(b[0]), "r"(b[1]));
}
__device__ __forceinline__ float ex2f(float x) {
    float y; asm("ex2.approx.ftz.f32 %0, %1;" : "=f"(y) : "f"(x)); return y;
}
__device__ __forceinline__ uint32_t packh2(float a, float b) {
    __half2 h = __floats2half2_rn(a, b);
    return *reinterpret_cast<uint32_t*>(&h);
}
#define CP16(dst, src) \
    asm volatile("cp.async.cg.shared.global [%0], [%1], 16;" :: "r"(dst), "l"(src))
#define CP_COMMIT() asm volatile("cp.async.commit_group;" ::: "memory")
#define CP_WAIT1()  asm volatile("cp.async.wait_group 1;" ::: "memory")
#define CP_WAIT0()  asm volatile("cp.async.wait_group 0;" ::: "memory")

// flash smem layout (bytes)
#define OFF_Q   0                    // 64 x 80 = 5120
#define OFF_K   5120                 // 2 bufs x 128 x 80 = 20480
#define OFF_VH  25600                // 2 bufs x 64 x 272 = 34816
#define SMEM_FLASH 60416
#define KBUF 10240
#define VBUF 17408
// epilogue reduction aliases (dead after mainloop)
#define OFF_RED  OFF_K               // 64 rows x 72 floats = 18432 <= 20480
#define RED_STRIDE 72
#define OFF_REDL OFF_VH              // 64 floats

// ---------------------------------------------------------------------------
// Phase 1 (fused): blocks [0,128): V' = concat @ W -> fp16 transposed [n][j].
//                  blocks [128,144): Q -> fp16 rows.   (unchanged)
// ---------------------------------------------------------------------------
__global__ __launch_bounds__(256, 2) void build_v_kernel(
    const float* __restrict__ review,
    const float* __restrict__ user, const float* __restrict__ item,
    const int* __restrict__ adj_ur, const int* __restrict__ adj_ri,
    const int* __restrict__ adj_ir, const int* __restrict__ adj_ru,
    const float* __restrict__ Wu, const float* __restrict__ Wi)
{
    const int side = blockIdx.y;
    const int tid = threadIdx.x;

    if (blockIdx.x >= NQ / 64) {
        const float* Q = side ? item : user;
        const int rbase = (blockIdx.x - NQ / 64) * 512;
#pragma unroll
        for (int rr = 0; rr < 2; rr++) {
            const int row = rbase + tid + rr * 256;
            const float4* src = reinterpret_cast<const float4*>(Q + (size_t)row * D);
            __half2* dst = reinterpret_cast<__half2*>(g_Qs + ((size_t)side * NQ + row) * 32);
#pragma unroll
            for (int s = 0; s < 8; s++) {
                const float4 v = __ldg(src + s);
                dst[s * 2 + 0] = __floats2half2_rn(v.x, v.y);
                dst[s * 2 + 1] = __floats2half2_rn(v.z, v.w);
            }
        }
        return;
    }

    extern __shared__ float cat[];                // [64][IN_DIM] = 64 KB
    const float* vecA = review;
    const int*   idxA = side ? adj_ir : adj_ur;
    const float* vecB = side ? user : item;
    const int*   idxB = side ? adj_ru : adj_ri;
    const float* W    = side ? Wi : Wu;
    const int u0 = blockIdx.x * 64;

    for (int t = tid; t < 64 * IN_DIM; t += 256) {
        const int lu = t >> 8, pos = t & 255, k = pos >> 6, w = pos & 63;
        const int gu = u0 + lu;
        float v;
        if (w < 32) v = vecA[idxA[gu * KNB + k] * D + w];
        else        v = vecB[idxB[gu * KNB + k] * D + (w - 32)];
        cat[lu * IN_DIM + pos] = v;
    }
    __syncthreads();

    const int cg  = tid & 15;
    const int ugb = (tid >> 4) * 4;
    const float4* Wg = reinterpret_cast<const float4*>(W);
    const float* c0 = cat + (ugb + 0) * IN_DIM;
    const float* c1 = cat + (ugb + 1) * IN_DIM;
    const float* c2 = cat + (ugb + 2) * IN_DIM;
    const float* c3 = cat + (ugb + 3) * IN_DIM;

    float a0[4], a1[4], a2[4], a3[4];
#pragma unroll
    for (int k = 0; k < 4; k++) { a0[k] = 0.f; a1[k] = 0.f; a2[k] = 0.f; a3[k] = 0.f; }

#pragma unroll 8
    for (int i = 0; i < IN_DIM; i++) {
        const float4 wv = __ldg(&Wg[i * 16 + cg]);
        const float v0 = c0[i], v1 = c1[i], v2 = c2[i], v3 = c3[i];
        a0[0] += v0 * wv.x; a0[1] += v0 * wv.y; a0[2] += v0 * wv.z; a0[3] += v0 * wv.w;
        a1[0] += v1 * wv.x; a1[1] += v1 * wv.y; a1[2] += v1 * wv.z; a1[3] += v1 * wv.w;
        a2[0] += v2 * wv.x; a2[1] += v2 * wv.y; a2[2] += v2 * wv.z; a2[3] += v2 * wv.w;
        a3[0] += v3 * wv.x; a3[1] += v3 * wv.y; a3[2] += v3 * wv.z; a3[3] += v3 * wv.w;
    }

    __half2* Vh = reinterpret_cast<__half2*>(g_Vth + (size_t)side * DV * NQ);
    const int jh2 = (u0 + ugb) >> 1;
#pragma unroll
    for (int k = 0; k < 4; k++) {
        const int n = cg * 4 + k;
        Vh[(size_t)n * (NQ / 2) + jh2]     = __floats2half2_rn(a0[k], a1[k]);
        Vh[(size_t)n * (NQ / 2) + jh2 + 1] = __floats2half2_rn(a2[k], a3[k]);
    }
}
#define SMEM_BUILD (64 * IN_DIM * 4)   // 64 KB

// ---------------------------------------------------------------------------
// Phase 2: all-fp16 HMMA flash attention.  BM=64, BN=128.
// 256 thr, 8 warps = (row-group w&3) x (j-half w>>2)  ->  16 warps/SM.
// Per warp-iter: 16 QK MMA + 32 exp + 32 PV MMA.  J-half combine in epilogue.
// ---------------------------------------------------------------------------
__global__ __launch_bounds__(256, 2) void flash_mma_kernel(float* __restrict__ out)
{
    extern __shared__ char smem[];
    const uint32_t sb = smem_u32(smem);
    const int tid = threadIdx.x;
    const int w = tid >> 5, lane = tid & 31;
    const int rw = w & 3;           // row group: rows 16*rw..+15
    const int jh = w >> 2;          // j-half: cols [64*jh, 64*jh+64) of the 128-tile
    const int side = blockIdx.y;
    const int bm0 = blockIdx.x * BM;

    const __half* Qside = g_Qs + (size_t)side * NQ * 32;
    const __half* VtH = g_Vth + (size_t)side * DV * NQ;

    // Q tile: 64 rows x 4 chunks = 256 -> 1/thread
    {
        int r = tid >> 2, seg = tid & 3;
        CP16(sb + OFF_Q + r * QSB + seg * 16,
             Qside + (size_t)(bm0 + r) * 32 + seg * 8);
    }
    // tile 0: K 128 rows x 4 chunks = 512 -> 2/thread; V 64 rows x 16 = 1024 -> 4/thread
#pragma unroll
    for (int i = 0; i < 2; i++) {
        int t = tid + 256 * i;
        int r = t >> 2, seg = t & 3;
        CP16(sb + OFF_K + r * QSB + seg * 16, Qside + (size_t)r * 32 + seg * 8);
    }
#pragma unroll
    for (int i = 0; i < 4; i++) {
        int t = tid + 256 * i;
        int r = t >> 4, seg = t & 15;
        CP16(sb + OFF_VH + r * VSB + seg * 16, VtH + (size_t)r * NQ + seg * 8);
    }
    CP_COMMIT();

    uint32_t qf[2][4];
    float o[8][4];
#pragma unroll
    for (int nt = 0; nt < 8; nt++)
#pragma unroll
        for (int i = 0; i < 4; i++) o[nt][i] = 0.f;
    float lsum0 = 0.f, lsum1 = 0.f;
    const float C  = 0.25503486f;    // log2(e)/sqrt(32)
    const float B2 = 11.5415603f;    // 8*log2(e)

    const int aRow = (lane & 7) + ((lane >> 3) & 1) * 8;
    const int aCol = ((lane >> 4) & 1) * 16;
    const int bRow = lane & 7;
    const int bCol = (lane >> 3) * 16;

    for (int it = 0; it < NITER; ++it) {
        const int cur = it & 1;
        if (it + 1 < NITER) {
            const int j0 = (it + 1) * BN;
            const int nb = (it + 1) & 1;
#pragma unroll
            for (int i = 0; i < 2; i++) {
                int t = tid + 256 * i;
                int r = t >> 2, seg = t & 3;
                CP16(sb + OFF_K + nb * KBUF + r * QSB + seg * 16,
                     Qside + (size_t)(j0 + r) * 32 + seg * 8);
            }
#pragma unroll
            for (int i = 0; i < 4; i++) {
                int t = tid + 256 * i;
                int r = t >> 4, seg = t & 15;
                CP16(sb + OFF_VH + nb * VBUF + r * VSB + seg * 16,
                     VtH + (size_t)r * NQ + j0 + seg * 8);
            }
            CP_COMMIT();
            CP_WAIT1();
        } else {
            CP_WAIT0();
        }
        __syncthreads();

        if (it == 0) {
            const uint32_t qbase = sb + OFF_Q + (16 * rw) * QSB + aRow * QSB + aCol;
            ldsm4(qf[0], qbase + 0);
            ldsm4(qf[1], qbase + 32);
        }

        // ---- S = Q K^T over this warp's 64 j-cols (fp16, 2 MMAs/nt) ----
        float s[8][4];
#pragma unroll
        for (int nt = 0; nt < 8; nt++)
#pragma unroll
            for (int i = 0; i < 4; i++) s[nt][i] = 0.f;

        const uint32_t kbase = sb + OFF_K + cur * KBUF + (jh * 64) * QSB
                             + bRow * QSB + bCol;
#pragma unroll
        for (int nt = 0; nt < 8; nt++) {
            uint32_t kh[4];
            ldsm4(kh, kbase + (8 * nt) * QSB);
            mma_fp16(s[nt], qf[0], kh + 0);
            mma_fp16(s[nt], qf[1], kh + 2);
        }

        // ---- exp (biased, unnormalized), partial row-sums, pack fp16 ----
#pragma unroll
        for (int nt = 0; nt < 8; nt++) {
#pragma unroll
            for (int i = 0; i < 4; i++) s[nt][i] = ex2f(s[nt][i] * C - B2);
            lsum0 += s[nt][0] + s[nt][1];
            lsum1 += s[nt][2] + s[nt][3];
        }
        uint32_t phi[4][4];
#pragma unroll
        for (int c = 0; c < 4; c++)
#pragma unroll
            for (int h = 0; h < 4; h++) {
                const int nt = 2 * c + (h >> 1);
                phi[c][h] = packh2(s[nt][(h & 1) * 2 + 0], s[nt][(h & 1) * 2 + 1]);
            }

        // ---- O += Ph @ Vh over this warp's j-half (4 k16 chunks) ----
        const uint32_t vhb = sb + OFF_VH + cur * VBUF + bRow * VSB + bCol + jh * 128;
#pragma unroll
        for (int nt = 0; nt < 8; nt++) {
            uint32_t vv[4];
            ldsm4(vv, vhb + (8 * nt) * VSB);         // chunks 0,1 of this half
            mma_fp16(o[nt], phi[0], vv + 0);
            mma_fp16(o[nt], phi[1], vv + 2);
            ldsm4(vv, vhb + (8 * nt) * VSB + 64);    // chunks 2,3
            mma_fp16(o[nt], phi[2], vv + 0);
            mma_fp16(o[nt], phi[3], vv + 2);
        }
        __syncthreads();
    }

    // ---- quad-reduce partial row sums within warp ----
    lsum0 += __shfl_xor_sync(0xffffffffu, lsum0, 1);
    lsum0 += __shfl_xor_sync(0xffffffffu, lsum0, 2);
    lsum1 += __shfl_xor_sync(0xffffffffu, lsum1, 1);
    lsum1 += __shfl_xor_sync(0xffffffffu, lsum1, 2);

    // ---- combine j-halves via smem (jh==1 ships to jh==0) ----
    const int lrow0 = 16 * rw + (lane >> 2);
    const int coff = 2 * (lane & 3);
    float* redO = reinterpret_cast<float*>(smem + OFF_RED);
    float* redL = reinterpret_cast<float*>(smem + OFF_REDL);

    if (jh == 1) {
#pragma unroll
        for (int nt = 0; nt < 8; nt++) {
            *reinterpret_cast<float2*>(&redO[lrow0 * RED_STRIDE + 8 * nt + coff]) =
                make_float2(o[nt][0], o[nt][1]);
            *reinterpret_cast<float2*>(&redO[(lrow0 + 8) * RED_STRIDE + 8 * nt + coff]) =
                make_float2(o[nt][2], o[nt][3]);
        }
        if ((lane & 3) == 0) {
            redL[lrow0] = lsum0;
            redL[lrow0 + 8] = lsum1;
        }
    }
    __syncthreads();

    if (jh == 0) {
        const float inv0 = 1.f / (lsum0 + redL[lrow0]);
        const float inv1 = 1.f / (lsum1 + redL[lrow0 + 8]);
        const int row0 = bm0 + lrow0;
        float* obase = out + (size_t)side * NQ * DV;
#pragma unroll
        for (int nt = 0; nt < 8; nt++) {
            const float2 r0 = *reinterpret_cast<float2*>(&redO[lrow0 * RED_STRIDE + 8 * nt + coff]);
            const float2 r1 = *reinterpret_cast<float2*>(&redO[(lrow0 + 8) * RED_STRIDE + 8 * nt + coff]);
            float2 v0 = make_float2(fmaxf((o[nt][0] + r0.x) * inv0, 0.f),
                                    fmaxf((o[nt][1] + r0.y) * inv0, 0.f));
            float2 v1 = make_float2(fmaxf((o[nt][2] + r1.x) * inv1, 0.f),
                                    fmaxf((o[nt][3] + r1.y) * inv1, 0.f));
            *reinterpret_cast<float2*>(obase + (size_t)row0 * DV + 8 * nt + coff) = v0;
            *reinterpret_cast<float2*>(obase + (size_t)(row0 + 8) * DV + 8 * nt + coff) = v1;
        }
    }
}

// ---------------------------------------------------------------------------
extern "C" void kernel_launch(void* const* d_in, const int* in_sizes, int n_in,
                              void* d_out, int out_size)
{
    (void)in_sizes; (void)n_in; (void)out_size;
    const float* review = (const float*)d_in[0];
    const float* user   = (const float*)d_in[1];
    const float* item   = (const float*)d_in[2];
    const int*   adj_ur = (const int*)d_in[3];
    const int*   adj_ri = (const int*)d_in[4];
    const int*   adj_ir = (const int*)d_in[5];
    const int*   adj_ru = (const int*)d_in[6];
    const float* Wu     = (const float*)d_in[7];
    const float* Wi     = (const float*)d_in[8];
    float* out = (float*)d_out;

    cudaFuncSetAttribute(build_v_kernel,
                         cudaFuncAttributeMaxDynamicSharedMemorySize, SMEM_BUILD);
    cudaFuncSetAttribute(flash_mma_kernel,
                         cudaFuncAttributeMaxDynamicSharedMemorySize, SMEM_FLASH);

    build_v_kernel<<<dim3(NQ / 64 + 16, 2), 256, SMEM_BUILD>>>(
        review, user, item, adj_ur, adj_ri, adj_ir, adj_ru, Wu, Wi);

    dim3 grid(NQ / BM, 2);
    flash_mma_kernel<<<grid, 256, SMEM_FLASH>>>(out);
}

// round 17
// speedup vs baseline: 1.0267x; 1.0267x over previous
#include <cuda_runtime.h>
#include <cuda_fp16.h>
#include <cstdint>

#define NQ 8192
#define D 32
#define DV 64
#define KNB 4
#define IN_DIM 256

#define BM 64
#define BN 128
#define NITER (NQ / BN)   // 64
#define QSB 80            // Q/K row: 64B data + 16B pad
#define VSB 144           // group V row: 128B data + 16B pad

// ---------------- device scratch ----------------
__device__ __half g_Qs[2 * NQ * 32];          // [side][row][0..31] fp16
__device__ __half g_Vth[2 * DV * NQ];         // [side][n][j] fp16

// ---------------- PTX helpers ----------------
__device__ __forceinline__ uint32_t smem_u32(const void* p) {
    uint32_t a;
    asm("{ .reg .u64 t; cvta.to.shared.u64 t, %1; cvt.u32.u64 %0, t; }" : "=r"(a) : "l"(p));
    return a;
}
__device__ __forceinline__ void ldsm4(uint32_t r[4], uint32_t addr) {
    asm volatile("ldmatrix.sync.aligned.m8n8.x4.shared.b16 {%0,%1,%2,%3}, [%4];"
                 : "=r"(r[0]), "=r"(r[1]), "=r"(r[2]), "=r"(r[3]) : "r"(addr));
}
__device__ __forceinline__ void mma_fp16(float d[4], const uint32_t a[4], const uint32_t b[2]) {
    asm volatile(
        "mma.sync.aligned.m16n8k16.row.col.f32.f16.f16.f32 "
        "{%0,%1,%2,%3}, {%4,%5,%6,%7}, {%8,%9}, {%0,%1,%2,%3};"
        : "+f"(d[0]), "+f"(d[1]), "+f"(d[2]), "+f"(d[3])
        : "r"(a[0]), "r"(a[1]), "r"(a[2]), "r"(a[3]), "r"(b[0]), "r"(b[1]));
}
__device__ __forceinline__ float ex2f(float x) {
    float y; asm("ex2.approx.ftz.f32 %0, %1;" : "=f"(y) : "f"(x)); return y;
}
__device__ __forceinline__ uint32_t packh2(float a, float b) {
    __half2 h = __floats2half2_rn(a, b);
    return *reinterpret_cast<uint32_t*>(&h);
}
#define CP16(dst, src) \
    asm volatile("cp.async.cg.shared.global [%0], [%1], 16;" :: "r"(dst), "l"(src))
#define CP_COMMIT() asm volatile("cp.async.commit_group;" ::: "memory")
#define CP_WAIT1()  asm volatile("cp.async.wait_group 1;" ::: "memory")
#define CP_WAIT0()  asm volatile("cp.async.wait_group 0;" ::: "memory")
#define GROUP_BAR(id) \
    asm volatile("bar.sync %0, 128;" :: "r"(id) : "memory")

// flash smem layout (bytes)
// Q: [0, 5120).  Group g region at 5120 + g*28672:
//   K bufs: +0, +5120 (64 rows x 80B each)
//   V bufs: +10240, +19456 (64 rows x 144B each)
#define OFF_Q   0
#define GRP0    5120
#define GRPSZ   28672
#define KBUF    5120
#define OFF_GV  10240
#define VBUF    9216
#define SMEM_FLASH 62464
// epilogue reduction aliases inside group-1 region (dead after mainloop)
#define OFF_RED  (GRP0 + GRPSZ)          // 33792: 64 rows x 72 floats = 18432
#define RED_STRIDE 72
#define OFF_REDL (OFF_RED + 18432)       // 52224: 64 floats

// ---------------------------------------------------------------------------
// Phase 1 (fused): blocks [0,128): V' = concat @ W -> fp16 transposed [n][j].
//                  blocks [128,144): Q -> fp16 rows.   (unchanged)
// ---------------------------------------------------------------------------
__global__ __launch_bounds__(256, 2) void build_v_kernel(
    const float* __restrict__ review,
    const float* __restrict__ user, const float* __restrict__ item,
    const int* __restrict__ adj_ur, const int* __restrict__ adj_ri,
    const int* __restrict__ adj_ir, const int* __restrict__ adj_ru,
    const float* __restrict__ Wu, const float* __restrict__ Wi)
{
    const int side = blockIdx.y;
    const int tid = threadIdx.x;

    if (blockIdx.x >= NQ / 64) {
        const float* Q = side ? item : user;
        const int rbase = (blockIdx.x - NQ / 64) * 512;
#pragma unroll
        for (int rr = 0; rr < 2; rr++) {
            const int row = rbase + tid + rr * 256;
            const float4* src = reinterpret_cast<const float4*>(Q + (size_t)row * D);
            __half2* dst = reinterpret_cast<__half2*>(g_Qs + ((size_t)side * NQ + row) * 32);
#pragma unroll
            for (int s = 0; s < 8; s++) {
                const float4 v = __ldg(src + s);
                dst[s * 2 + 0] = __floats2half2_rn(v.x, v.y);
                dst[s * 2 + 1] = __floats2half2_rn(v.z, v.w);
            }
        }
        return;
    }

    extern __shared__ float cat[];                // [64][IN_DIM] = 64 KB
    const float* vecA = review;
    const int*   idxA = side ? adj_ir : adj_ur;
    const float* vecB = side ? user : item;
    const int*   idxB = side ? adj_ru : adj_ri;
    const float* W    = side ? Wi : Wu;
    const int u0 = blockIdx.x * 64;

    for (int t = tid; t < 64 * IN_DIM; t += 256) {
        const int lu = t >> 8, pos = t & 255, k = pos >> 6, w = pos & 63;
        const int gu = u0 + lu;
        float v;
        if (w < 32) v = vecA[idxA[gu * KNB + k] * D + w];
        else        v = vecB[idxB[gu * KNB + k] * D + (w - 32)];
        cat[lu * IN_DIM + pos] = v;
    }
    __syncthreads();

    const int cg  = tid & 15;
    const int ugb = (tid >> 4) * 4;
    const float4* Wg = reinterpret_cast<const float4*>(W);
    const float* c0 = cat + (ugb + 0) * IN_DIM;
    const float* c1 = cat + (ugb + 1) * IN_DIM;
    const float* c2 = cat + (ugb + 2) * IN_DIM;
    const float* c3 = cat + (ugb + 3) * IN_DIM;

    float a0[4], a1[4], a2[4], a3[4];
#pragma unroll
    for (int k = 0; k < 4; k++) { a0[k] = 0.f; a1[k] = 0.f; a2[k] = 0.f; a3[k] = 0.f; }

#pragma unroll 8
    for (int i = 0; i < IN_DIM; i++) {
        const float4 wv = __ldg(&Wg[i * 16 + cg]);
        const float v0 = c0[i], v1 = c1[i], v2 = c2[i], v3 = c3[i];
        a0[0] += v0 * wv.x; a0[1] += v0 * wv.y; a0[2] += v0 * wv.z; a0[3] += v0 * wv.w;
        a1[0] += v1 * wv.x; a1[1] += v1 * wv.y; a1[2] += v1 * wv.z; a1[3] += v1 * wv.w;
        a2[0] += v2 * wv.x; a2[1] += v2 * wv.y; a2[2] += v2 * wv.z; a2[3] += v2 * wv.w;
        a3[0] += v3 * wv.x; a3[1] += v3 * wv.y; a3[2] += v3 * wv.z; a3[3] += v3 * wv.w;
    }

    __half2* Vh = reinterpret_cast<__half2*>(g_Vth + (size_t)side * DV * NQ);
    const int jh2 = (u0 + ugb) >> 1;
#pragma unroll
    for (int k = 0; k < 4; k++) {
        const int n = cg * 4 + k;
        Vh[(size_t)n * (NQ / 2) + jh2]     = __floats2half2_rn(a0[k], a1[k]);
        Vh[(size_t)n * (NQ / 2) + jh2 + 1] = __floats2half2_rn(a2[k], a3[k]);
    }
}
#define SMEM_BUILD (64 * IN_DIM * 4)   // 64 KB

// ---------------------------------------------------------------------------
// Phase 2: all-fp16 HMMA flash attention.  BM=64, BN=128.
// 256 thr, 8 warps = (row-group w&3) x (j-half w>>2).
// Each 128-thread j-group owns private K/V smem slices and syncs only with
// bar.sync(1+jh,128) -> the two groups' phases drift and overlap pipes.
// ---------------------------------------------------------------------------
__global__ __launch_bounds__(256, 2) void flash_mma_kernel(float* __restrict__ out)
{
    extern __shared__ char smem[];
    const uint32_t sb = smem_u32(smem);
    const int tid = threadIdx.x;
    const int w = tid >> 5, lane = tid & 31;
    const int rw = w & 3;           // row group: rows 16*rw..+15
    const int jh = w >> 2;          // j-half group id (0/1)
    const int tid_g = tid & 127;    // lane within group
    const int side = blockIdx.y;
    const int bm0 = blockIdx.x * BM;

    const __half* Qside = g_Qs + (size_t)side * NQ * 32;
    const __half* VtH = g_Vth + (size_t)side * DV * NQ;
    const uint32_t gB = sb + GRP0 + (uint32_t)jh * GRPSZ;   // this group's region

    // Q tile: 64 rows x 4 chunks = 256 -> 1/thread (shared by both groups)
    {
        int r = tid >> 2, seg = tid & 3;
        CP16(sb + OFF_Q + r * QSB + seg * 16,
             Qside + (size_t)(bm0 + r) * 32 + seg * 8);
    }
    // tile 0, group slices: K rows [jh*64,+64) -> 2/thread; V j-half -> 4/thread
#pragma unroll
    for (int i = 0; i < 2; i++) {
        int t = tid_g + 128 * i;
        int r = t >> 2, seg = t & 3;
        CP16(gB + r * QSB + seg * 16,
             Qside + (size_t)(jh * 64 + r) * 32 + seg * 8);
    }
#pragma unroll
    for (int i = 0; i < 4; i++) {
        int t = tid_g + 128 * i;
        int r = t >> 3, seg = t & 7;
        CP16(gB + OFF_GV + r * VSB + seg * 16,
             VtH + (size_t)r * NQ + jh * 64 + seg * 8);
    }
    CP_COMMIT();
    CP_WAIT0();
    __syncthreads();    // Q + tile0 fully visible to both groups

    uint32_t qf[2][4];
    float o[8][4];
#pragma unroll
    for (int nt = 0; nt < 8; nt++)
#pragma unroll
        for (int i = 0; i < 4; i++) o[nt][i] = 0.f;
    float lsum0 = 0.f, lsum1 = 0.f;
    const float C  = 0.25503486f;    // log2(e)/sqrt(32)
    const float B2 = 11.5415603f;    // 8*log2(e)

    const int aRow = (lane & 7) + ((lane >> 3) & 1) * 8;
    const int aCol = ((lane >> 4) & 1) * 16;
    const int bRow = lane & 7;
    const int bCol = (lane >> 3) * 16;

    // persistent Q fragments
    {
        const uint32_t qbase = sb + OFF_Q + (16 * rw) * QSB + aRow * QSB + aCol;
        ldsm4(qf[0], qbase + 0);
        ldsm4(qf[1], qbase + 32);
    }

    const int barid = 1 + jh;

    for (int it = 0; it < NITER; ++it) {
        const int cur = it & 1;
        if (it + 1 < NITER) {
            const int j0 = (it + 1) * BN;
            const int nb = (it + 1) & 1;
#pragma unroll
            for (int i = 0; i < 2; i++) {
                int t = tid_g + 128 * i;
                int r = t >> 2, seg = t & 3;
                CP16(gB + nb * KBUF + r * QSB + seg * 16,
                     Qside + (size_t)(j0 + jh * 64 + r) * 32 + seg * 8);
            }
#pragma unroll
            for (int i = 0; i < 4; i++) {
                int t = tid_g + 128 * i;
                int r = t >> 3, seg = t & 7;
                CP16(gB + OFF_GV + nb * VBUF + r * VSB + seg * 16,
                     VtH + (size_t)r * NQ + j0 + jh * 64 + seg * 8);
            }
            CP_COMMIT();
            CP_WAIT1();
        } else {
            CP_WAIT0();
        }
        GROUP_BAR(barid);

        // ---- S = Q K^T over this group's 64 j-cols (fp16, 2 MMAs/nt) ----
        float s[8][4];
#pragma unroll
        for (int nt = 0; nt < 8; nt++)
#pragma unroll
            for (int i = 0; i < 4; i++) s[nt][i] = 0.f;

        const uint32_t kbase = gB + cur * KBUF + bRow * QSB + bCol;
#pragma unroll
        for (int nt = 0; nt < 8; nt++) {
            uint32_t kh[4];
            ldsm4(kh, kbase + (8 * nt) * QSB);
            mma_fp16(s[nt], qf[0], kh + 0);
            mma_fp16(s[nt], qf[1], kh + 2);
        }

        // ---- exp (biased, unnormalized), partial row-sums, pack fp16 ----
#pragma unroll
        for (int nt = 0; nt < 8; nt++) {
#pragma unroll
            for (int i = 0; i < 4; i++) s[nt][i] = ex2f(s[nt][i] * C - B2);
            lsum0 += s[nt][0] + s[nt][1];
            lsum1 += s[nt][2] + s[nt][3];
        }
        uint32_t phi[4][4];
#pragma unroll
        for (int c = 0; c < 4; c++)
#pragma unroll
            for (int h = 0; h < 4; h++) {
                const int nt = 2 * c + (h >> 1);
                phi[c][h] = packh2(s[nt][(h & 1) * 2 + 0], s[nt][(h & 1) * 2 + 1]);
            }

        // ---- O += Ph @ Vh over this group's j-half (4 k16 chunks) ----
        const uint32_t vhb = gB + OFF_GV + cur * VBUF + bRow * VSB + bCol;
#pragma unroll
        for (int nt = 0; nt < 8; nt++) {
            uint32_t vv[4];
            ldsm4(vv, vhb + (8 * nt) * VSB);         // k16 chunks 0,1
            mma_fp16(o[nt], phi[0], vv + 0);
            mma_fp16(o[nt], phi[1], vv + 2);
            ldsm4(vv, vhb + (8 * nt) * VSB + 64);    // k16 chunks 2,3
            mma_fp16(o[nt], phi[2], vv + 0);
            mma_fp16(o[nt], phi[3], vv + 2);
        }
        GROUP_BAR(barid);
    }

    // ---- quad-reduce partial row sums within warp ----
    lsum0 += __shfl_xor_sync(0xffffffffu, lsum0, 1);
    lsum0 += __shfl_xor_sync(0xffffffffu, lsum0, 2);
    lsum1 += __shfl_xor_sync(0xffffffffu, lsum1, 1);
    lsum1 += __shfl_xor_sync(0xffffffffu, lsum1, 2);

    // ---- combine j-halves via smem (jh==1 ships to jh==0) ----
    __syncthreads();   // both groups done with their regions
    const int lrow0 = 16 * rw + (lane >> 2);
    const int coff = 2 * (lane & 3);
    float* redO = reinterpret_cast<float*>(smem + OFF_RED);
    float* redL = reinterpret_cast<float*>(smem + OFF_REDL);

    if (jh == 1) {
#pragma unroll
        for (int nt = 0; nt < 8; nt++) {
            *reinterpret_cast<float2*>(&redO[lrow0 * RED_STRIDE + 8 * nt + coff]) =
                make_float2(o[nt][0], o[nt][1]);
            *reinterpret_cast<float2*>(&redO[(lrow0 + 8) * RED_STRIDE + 8 * nt + coff]) =
                make_float2(o[nt][2], o[nt][3]);
        }
        if ((lane & 3) == 0) {
            redL[lrow0] = lsum0;
            redL[lrow0 + 8] = lsum1;
        }
    }
    __syncthreads();

    if (jh == 0) {
        const float inv0 = 1.f / (lsum0 + redL[lrow0]);
        const float inv1 = 1.f / (lsum1 + redL[lrow0 + 8]);
        const int row0 = bm0 + lrow0;
        float* obase = out + (size_t)side * NQ * DV;
#pragma unroll
        for (int nt = 0; nt < 8; nt++) {
            const float2 r0 = *reinterpret_cast<float2*>(&redO[lrow0 * RED_STRIDE + 8 * nt + coff]);
            const float2 r1 = *reinterpret_cast<float2*>(&redO[(lrow0 + 8) * RED_STRIDE + 8 * nt + coff]);
            float2 v0 = make_float2(fmaxf((o[nt][0] + r0.x) * inv0, 0.f),
                                    fmaxf((o[nt][1] + r0.y) * inv0, 0.f));
            float2 v1 = make_float2(fmaxf((o[nt][2] + r1.x) * inv1, 0.f),
                                    fmaxf((o[nt][3] + r1.y) * inv1, 0.f));
            *reinterpret_cast<float2*>(obase + (size_t)row0 * DV + 8 * nt + coff) = v0;
            *reinterpret_cast<float2*>(obase + (size_t)(row0 + 8) * DV + 8 * nt + coff) = v1;
        }
    }
}

// ---------------------------------------------------------------------------
extern "C" void kernel_launch(void* const* d_in, const int* in_sizes, int n_in,
                              void* d_out, int out_size)
{
    (void)in_sizes; (void)n_in; (void)out_size;
    const float* review = (const float*)d_in[0];
    const float* user   = (const float*)d_in[1];
    const float* item   = (const float*)d_in[2];
    const int*   adj_ur = (const int*)d_in[3];
    const int*   adj_ri = (const int*)d_in[4];
    const int*   adj_ir = (const int*)d_in[5];
    const int*   adj_ru = (const int*)d_in[6];
    const float* Wu     = (const float*)d_in[7];
    const float* Wi     = (const float*)d_in[8];
    float* out = (float*)d_out;

    cudaFuncSetAttribute(build_v_kernel,
                         cudaFuncAttributeMaxDynamicSharedMemorySize, SMEM_BUILD);
    cudaFuncSetAttribute(flash_mma_kernel,
                         cudaFuncAttributeMaxDynamicSharedMemorySize, SMEM_FLASH);

    build_v_kernel<<<dim3(NQ / 64 + 16, 2), 256, SMEM_BUILD>>>(
        review, user, item, adj_ur, adj_ri, adj_ir, adj_ru, Wu, Wi);

    dim3 grid(NQ / BM, 2);
    flash_mma_kernel<<<grid, 256, SMEM_FLASH>>>(out);
}